// round 1
// baseline (speedup 1.0000x reference)
#include <cuda_runtime.h>

// FastQuantumLLMOptimized: per-position cross-head attention.
// x: [B*L, 32, 128] f32 (B*L = 16384), patterns: [32,128] f32.
// Per position p:
//   xh[h][d]   = x[p][h][d] * patterns[h][d]
//   s[h][g]    = (sum_d xh[h][d]*xh[g][d]) / sqrt(128)
//   a[h][:]    = softmax(s[h][:])
//   out[h][d]  = sum_g a[h][g]*xh[g][d]
//
// One CTA of 128 threads per position. All math fp32; inner loops use packed
// fma.rn.f32x2 (FFMA2) for 2x fp32 FMA throughput on sm_103a.

#define NHEADS 32
#define HD 128
#define XH_STRIDE 132     // padded row stride (floats) for conflict-free row access
#define PART_STRIDE 33    // padded stride for score/attn rows (bank-conflict-free)

__device__ __forceinline__ unsigned long long pack2(float lo, float hi) {
    unsigned long long r;
    asm("mov.b64 %0, {%1, %2};" : "=l"(r) : "f"(lo), "f"(hi));
    return r;
}
__device__ __forceinline__ float2 unpack2(unsigned long long v) {
    float2 r;
    asm("mov.b64 {%0, %1}, %2;" : "=f"(r.x), "=f"(r.y) : "l"(v));
    return r;
}
__device__ __forceinline__ void fma2(unsigned long long &acc,
                                     unsigned long long a,
                                     unsigned long long b) {
    asm("fma.rn.f32x2 %0, %1, %2, %0;" : "+l"(acc) : "l"(a), "l"(b));
}

__global__ __launch_bounds__(128)
void fq_attn_kernel(const float* __restrict__ x,
                    const float* __restrict__ patterns,
                    float* __restrict__ out)
{
    __shared__ __align__(16) float s_xh[NHEADS * XH_STRIDE];          // 16896 B
    __shared__ __align__(16) float s_part[4 * NHEADS * PART_STRIDE];  // 16896 B
    __shared__ __align__(16) float s_attn[NHEADS * PART_STRIDE];      //  4224 B

    const int tid = threadIdx.x;
    const long long pos = blockIdx.x;

    // ---------------- Phase 1: load x row, modulate by patterns -> smem ----
    {
        const float4* x4 = reinterpret_cast<const float4*>(x + pos * (NHEADS * HD));
        const float4* p4 = reinterpret_cast<const float4*>(patterns);
        #pragma unroll
        for (int i = 0; i < 8; i++) {
            int idx = tid + i * 128;           // float4 index 0..1023
            float4 xv = x4[idx];
            float4 pv = __ldg(&p4[idx]);       // patterns float4 index == idx
            int h  = idx >> 5;                 // 32 float4 per head row
            int dd = (idx & 31) << 2;
            float4 r;
            r.x = xv.x * pv.x; r.y = xv.y * pv.y;
            r.z = xv.z * pv.z; r.w = xv.w * pv.w;
            *reinterpret_cast<float4*>(&s_xh[h * XH_STRIDE + dd]) = r;
        }
    }
    __syncthreads();

    // ---------------- Phase 2: scores = xh @ xh^T (32x32, k=128) -----------
    // 32 tiles of 4h x 8g, each tile split over 4 k-chunks (k=32 each).
    {
        const int kt   = tid & 3;              // k-chunk 0..3
        const int tile = tid >> 2;             // 0..31
        const int h0   = (tile >> 2) * 4;      // 0,4,...,28
        const int g0   = (tile & 3) * 8;       // 0,8,16,24
        const int kb   = kt * 32;

        unsigned long long acc[4][8];
        #pragma unroll
        for (int i = 0; i < 4; i++)
            #pragma unroll
            for (int j = 0; j < 8; j++) acc[i][j] = 0ULL;

        #pragma unroll
        for (int s = 0; s < 8; s++) {
            const int k = kb + s * 4;
            ulonglong2 a[4];
            #pragma unroll
            for (int i = 0; i < 4; i++)
                a[i] = *reinterpret_cast<const ulonglong2*>(&s_xh[(h0 + i) * XH_STRIDE + k]);
            #pragma unroll
            for (int j = 0; j < 8; j++) {
                ulonglong2 b = *reinterpret_cast<const ulonglong2*>(&s_xh[(g0 + j) * XH_STRIDE + k]);
                #pragma unroll
                for (int i = 0; i < 4; i++) {
                    fma2(acc[i][j], a[i].x, b.x);
                    fma2(acc[i][j], a[i].y, b.y);
                }
            }
        }
        #pragma unroll
        for (int i = 0; i < 4; i++)
            #pragma unroll
            for (int j = 0; j < 8; j++) {
                float2 u = unpack2(acc[i][j]);
                s_part[kt * (NHEADS * PART_STRIDE) + (h0 + i) * PART_STRIDE + (g0 + j)]
                    = u.x + u.y;
            }
    }
    __syncthreads();

    // ---------------- Phase 3: combine k-partials + softmax ----------------
    // 4 threads per row; each owns 8 columns; reduce within 4-lane group.
    {
        const int r = tid >> 2;    // row 0..31
        const int q = tid & 3;     // column group 0..3
        float v[8];
        #pragma unroll
        for (int j = 0; j < 8; j++) {
            const int g = q * 8 + j;
            float sum = s_part[0 * (NHEADS * PART_STRIDE) + r * PART_STRIDE + g]
                      + s_part[1 * (NHEADS * PART_STRIDE) + r * PART_STRIDE + g]
                      + s_part[2 * (NHEADS * PART_STRIDE) + r * PART_STRIDE + g]
                      + s_part[3 * (NHEADS * PART_STRIDE) + r * PART_STRIDE + g];
            v[j] = sum * 0.08838834764831845f;   // 1/sqrt(128)
        }
        float m = v[0];
        #pragma unroll
        for (int j = 1; j < 8; j++) m = fmaxf(m, v[j]);
        m = fmaxf(m, __shfl_xor_sync(0xffffffffu, m, 1));
        m = fmaxf(m, __shfl_xor_sync(0xffffffffu, m, 2));
        float ssum = 0.0f;
        #pragma unroll
        for (int j = 0; j < 8; j++) { v[j] = __expf(v[j] - m); ssum += v[j]; }
        ssum += __shfl_xor_sync(0xffffffffu, ssum, 1);
        ssum += __shfl_xor_sync(0xffffffffu, ssum, 2);
        const float inv = 1.0f / ssum;
        #pragma unroll
        for (int j = 0; j < 8; j++)
            s_attn[r * PART_STRIDE + q * 8 + j] = v[j] * inv;
    }
    __syncthreads();

    // ---------------- Phase 4: out = attn @ xh (32x128, k=32) --------------
    // 128 threads: 8 h-tiles (4 rows) x 16 d-tiles (8 cols).
    {
        const int ht = tid >> 4;       // 0..7
        const int dt = tid & 15;       // 0..15
        const int h0 = ht * 4;
        const int d0 = dt * 8;

        unsigned long long acc[4][4];
        #pragma unroll
        for (int i = 0; i < 4; i++)
            #pragma unroll
            for (int jp = 0; jp < 4; jp++) acc[i][jp] = 0ULL;

        #pragma unroll 8
        for (int g = 0; g < 32; g++) {
            ulonglong2 b01 = *reinterpret_cast<const ulonglong2*>(&s_xh[g * XH_STRIDE + d0]);
            ulonglong2 b23 = *reinterpret_cast<const ulonglong2*>(&s_xh[g * XH_STRIDE + d0 + 4]);
            #pragma unroll
            for (int i = 0; i < 4; i++) {
                float av = s_attn[(h0 + i) * PART_STRIDE + g];
                unsigned long long a2 = pack2(av, av);
                fma2(acc[i][0], a2, b01.x);
                fma2(acc[i][1], a2, b01.y);
                fma2(acc[i][2], a2, b23.x);
                fma2(acc[i][3], a2, b23.y);
            }
        }

        float* outp = out + pos * (NHEADS * HD);
        #pragma unroll
        for (int i = 0; i < 4; i++) {
            float2 u0 = unpack2(acc[i][0]);
            float2 u1 = unpack2(acc[i][1]);
            float2 u2 = unpack2(acc[i][2]);
            float2 u3 = unpack2(acc[i][3]);
            float4 o0 = make_float4(u0.x, u0.y, u1.x, u1.y);
            float4 o1 = make_float4(u2.x, u2.y, u3.x, u3.y);
            *reinterpret_cast<float4*>(&outp[(h0 + i) * HD + d0])     = o0;
            *reinterpret_cast<float4*>(&outp[(h0 + i) * HD + d0 + 4]) = o1;
        }
    }
}

extern "C" void kernel_launch(void* const* d_in, const int* in_sizes, int n_in,
                              void* d_out, int out_size) {
    const float* x        = (const float*)d_in[0];
    const float* patterns = (const float*)d_in[1];
    float* out            = (float*)d_out;
    const int positions   = in_sizes[0] / (NHEADS * HD);   // 16384
    fq_attn_kernel<<<positions, 128>>>(x, patterns, out);
}

// round 2
// speedup vs baseline: 3.5481x; 3.5481x over previous
#include <cuda_runtime.h>

// FastQuantumLLMOptimized: per-position cross-head attention.
// x: [16384, 32, 128] f32, patterns: [32,128] f32.
//   xh = x_pos * patterns ; s = xh @ xh^T / sqrt(128); a = softmax(s); out = a @ xh
//
// One CTA (128 thr) per position. fp32 math with packed fma.rn.f32x2.
// All shared-memory access patterns are bank-conflict-free by construction:
//  - xh stored as float4 granules with XOR swizzle P(h,c)=h*32+(c^((h&8)>>1))
//  - phase-2 k-split is interleaved (thread kt owns chunks kt+4s)
//  - partials buffer chunk stride 1057 (== 1 mod 32)

#define NHEADS 32
#define HD 128
#define SWZ(h) (((h) & 8) >> 1)     // granule XOR: 0 or 4
#define PS_ROW 33
#define PS_CH  1057                  // 32*33 + 1  (chunk stride, == 1 mod 32)
#define AT_ROW 36                    // attn row stride: 144B, 16B-aligned

__device__ __forceinline__ unsigned long long pack2(float lo, float hi) {
    unsigned long long r;
    asm("mov.b64 %0, {%1, %2};" : "=l"(r) : "f"(lo), "f"(hi));
    return r;
}
__device__ __forceinline__ float2 unpack2(unsigned long long v) {
    float2 r;
    asm("mov.b64 {%0, %1}, %2;" : "=f"(r.x), "=f"(r.y) : "l"(v));
    return r;
}
__device__ __forceinline__ void fma2(unsigned long long &acc,
                                     unsigned long long a,
                                     unsigned long long b) {
    asm("fma.rn.f32x2 %0, %1, %2, %0;" : "+l"(acc) : "l"(a), "l"(b));
}

__global__ __launch_bounds__(128)
void fq_attn_kernel(const float* __restrict__ x,
                    const float* __restrict__ patterns,
                    float* __restrict__ out)
{
    __shared__ __align__(16) float4 s_xh4[NHEADS * 32];                 // 16 KB
    __shared__ float s_part[3 * PS_CH + NHEADS * PS_ROW];               // ~16.5 KB
    __shared__ __align__(16) float s_attn[NHEADS * AT_ROW];             // 4.5 KB

    const int tid = threadIdx.x;
    const long long pos = blockIdx.x;

    // ---------------- Phase 1: load + modulate -> swizzled smem ------------
    {
        const float4* x4 = reinterpret_cast<const float4*>(x + pos * (NHEADS * HD));
        const float4* p4 = reinterpret_cast<const float4*>(patterns);
        #pragma unroll
        for (int i = 0; i < 8; i++) {
            int idx = tid + i * 128;          // float4 index 0..1023
            float4 xv = x4[idx];
            float4 pv = __ldg(&p4[idx]);
            int h = idx >> 5;                 // warp-uniform row
            int c = idx & 31;                 // lane = chunk -> conflict-free
            float4 r;
            r.x = xv.x * pv.x; r.y = xv.y * pv.y;
            r.z = xv.z * pv.z; r.w = xv.w * pv.w;
            s_xh4[h * 32 + (c ^ SWZ(h))] = r;
        }
    }
    __syncthreads();

    // ---------------- Phase 2: scores = xh @ xh^T (32x32, k=128) -----------
    // 128 threads = kt(4, interleaved k) x gt(4, 8 g-rows) x ht(8, 4 h-rows).
    {
        const int kt = tid & 3;
        const int gt = (tid >> 2) & 3;
        const int ht = tid >> 4;
        const int h0 = ht * 4;
        const int g0 = gt * 8;
        const int sa = SWZ(h0);     // uniform over i (h0..h0+3 share bit 3)
        const int sb = SWZ(g0);     // uniform over j (g0..g0+7 share bit 3)

        unsigned long long acc[4][8];
        #pragma unroll
        for (int i = 0; i < 4; i++)
            #pragma unroll
            for (int j = 0; j < 8; j++) acc[i][j] = 0ULL;

        #pragma unroll
        for (int s = 0; s < 8; s++) {
            const int c = kt + 4 * s;          // interleaved k-chunk
            ulonglong2 a[4];
            #pragma unroll
            for (int i = 0; i < 4; i++)
                a[i] = *reinterpret_cast<const ulonglong2*>(&s_xh4[(h0 + i) * 32 + (c ^ sa)]);
            #pragma unroll
            for (int j = 0; j < 8; j++) {
                ulonglong2 b = *reinterpret_cast<const ulonglong2*>(&s_xh4[(g0 + j) * 32 + (c ^ sb)]);
                #pragma unroll
                for (int i = 0; i < 4; i++) {
                    fma2(acc[i][j], a[i].x, b.x);
                    fma2(acc[i][j], a[i].y, b.y);
                }
            }
        }
        #pragma unroll
        for (int i = 0; i < 4; i++)
            #pragma unroll
            for (int j = 0; j < 8; j++) {
                float2 u = unpack2(acc[i][j]);
                // banks: kt*1 + ht_low*4 + gt*8 -> all 32 lanes distinct
                s_part[kt * PS_CH + (h0 + i) * PS_ROW + (g0 + j)] = u.x + u.y;
            }
    }
    __syncthreads();

    // ---------------- Phase 3: combine partials + softmax ------------------
    {
        const int r = tid >> 2;    // row 0..31
        const int q = tid & 3;     // column group
        float v[8];
        #pragma unroll
        for (int j = 0; j < 8; j++) {
            const int g = q * 8 + j;
            float sum = s_part[0 * PS_CH + r * PS_ROW + g]
                      + s_part[1 * PS_CH + r * PS_ROW + g]
                      + s_part[2 * PS_CH + r * PS_ROW + g]
                      + s_part[3 * PS_CH + r * PS_ROW + g];
            v[j] = sum * 0.08838834764831845f;   // 1/sqrt(128)
        }
        float m = v[0];
        #pragma unroll
        for (int j = 1; j < 8; j++) m = fmaxf(m, v[j]);
        m = fmaxf(m, __shfl_xor_sync(0xffffffffu, m, 1));
        m = fmaxf(m, __shfl_xor_sync(0xffffffffu, m, 2));
        float ssum = 0.0f;
        #pragma unroll
        for (int j = 0; j < 8; j++) { v[j] = __expf(v[j] - m); ssum += v[j]; }
        ssum += __shfl_xor_sync(0xffffffffu, ssum, 1);
        ssum += __shfl_xor_sync(0xffffffffu, ssum, 2);
        const float inv = 1.0f / ssum;
        #pragma unroll
        for (int j = 0; j < 8; j++)
            s_attn[r * AT_ROW + q * 8 + j] = v[j] * inv;
    }
    __syncthreads();

    // ---------------- Phase 4: out = attn @ xh (32x128, k=32) --------------
    // 128 threads = dt(16) x ht(8).  Each thread owns d-chunks {dt, dt+16}
    // (4 floats each) so 8-lane phase groups cover granules 0..7 exactly.
    {
        const int dt = tid & 15;
        const int ht = tid >> 4;
        const int h0 = ht * 4;

        unsigned long long acc[4][4];
        #pragma unroll
        for (int i = 0; i < 4; i++)
            #pragma unroll
            for (int jp = 0; jp < 4; jp++) acc[i][jp] = 0ULL;

        #pragma unroll
        for (int gb = 0; gb < 8; gb++) {
            float4 at[4];
            #pragma unroll
            for (int i = 0; i < 4; i++)    // warp-broadcast loads
                at[i] = *reinterpret_cast<const float4*>(&s_attn[(h0 + i) * AT_ROW + gb * 4]);
            #pragma unroll
            for (int t = 0; t < 4; t++) {
                const int g = gb * 4 + t;
                const int sg = SWZ(g);
                ulonglong2 b0 = *reinterpret_cast<const ulonglong2*>(&s_xh4[g * 32 + (dt ^ sg)]);
                ulonglong2 b1 = *reinterpret_cast<const ulonglong2*>(&s_xh4[g * 32 + ((dt + 16) ^ sg)]);
                #pragma unroll
                for (int i = 0; i < 4; i++) {
                    float av = (&at[i].x)[t];
                    unsigned long long a2 = pack2(av, av);
                    fma2(acc[i][0], a2, b0.x);
                    fma2(acc[i][1], a2, b0.y);
                    fma2(acc[i][2], a2, b1.x);
                    fma2(acc[i][3], a2, b1.y);
                }
            }
        }

        float* outp = out + pos * (NHEADS * HD);
        #pragma unroll
        for (int i = 0; i < 4; i++) {
            float2 u0 = unpack2(acc[i][0]);
            float2 u1 = unpack2(acc[i][1]);
            float2 u2 = unpack2(acc[i][2]);
            float2 u3 = unpack2(acc[i][3]);
            float4 o0 = make_float4(u0.x, u0.y, u1.x, u1.y);
            float4 o1 = make_float4(u2.x, u2.y, u3.x, u3.y);
            *reinterpret_cast<float4*>(&outp[(h0 + i) * HD + dt * 4])      = o0;
            *reinterpret_cast<float4*>(&outp[(h0 + i) * HD + dt * 4 + 64]) = o1;
        }
    }
}

extern "C" void kernel_launch(void* const* d_in, const int* in_sizes, int n_in,
                              void* d_out, int out_size) {
    const float* x        = (const float*)d_in[0];
    const float* patterns = (const float*)d_in[1];
    float* out            = (float*)d_out;
    const int positions   = in_sizes[0] / (NHEADS * HD);   // 16384
    fq_attn_kernel<<<positions, 128>>>(x, patterns, out);
}